// round 5
// baseline (speedup 1.0000x reference)
#include <cuda_runtime.h>
#include <cstdint>
#include <cfloat>

// Problem constants
#define NF    1024
#define BATCH 1024
#define HW    64
#define PIX   (HW * HW)     // 4096
#define PAD   3
#define PW    70            // padded side
#define PPIX  (PW * PW)     // 4900
#define FHALF 512           // filters per block
#define FITER 4             // 512 / 128 threads

// ---------------------------------------------------------------------------
// Packed f32x2 helpers (Blackwell packed-FP32 pipe: 2x FFMA throughput)
// ---------------------------------------------------------------------------
__device__ __forceinline__ unsigned long long ffma2(unsigned long long a,
                                                    unsigned long long b,
                                                    unsigned long long c) {
    unsigned long long d;
    asm("fma.rn.f32x2 %0, %1, %2, %3;" : "=l"(d) : "l"(a), "l"(b), "l"(c));
    return d;
}
__device__ __forceinline__ unsigned long long fmul2(unsigned long long a,
                                                    unsigned long long b) {
    unsigned long long d;
    asm("mul.rn.f32x2 %0, %1, %2;" : "=l"(d) : "l"(a), "l"(b));
    return d;
}
__device__ __forceinline__ unsigned long long pack2(float x, float y) {
    unsigned long long r;
    asm("mov.b64 %0, {%1, %2};" : "=l"(r) : "f"(x), "f"(y));
    return r;
}
__device__ __forceinline__ float2 unpack2(unsigned long long v) {
    float2 r;
    asm("mov.b64 {%0, %1}, %2;" : "=f"(r.x), "=f"(r.y) : "l"(v));
    return r;
}

// ---------------------------------------------------------------------------
// Fused kernel: block = (batch-pair, filter-half).
//  1. Build zero-padded 70x70x2 image slab in SMEM from X (coalesced).
//  2. For each of 512 filters: 5x5 conv on the 6x6 outputs the pool reads
//     (window rows via LDS.64 immediate-offset), bias + 3x3/3 maxpool, store.
// All math is packed f32x2 (lane .x = batch b0, .y = b0+1).
// ---------------------------------------------------------------------------
__global__ void __launch_bounds__(128, 3) filters_fused_kernel(
    const float* __restrict__ X,      // [B, 4096]
    const float* __restrict__ W,      // [NF, 25]
    const float* __restrict__ bias,   // [NF]
    const int*   __restrict__ pos,    // [NF, 2]
    float*       __restrict__ out)    // [B, NF*4]
{
    __shared__ float slab[PPIX * 2];  // [padded_pixel][2 batches] = 39.2 KB

    const int tid = threadIdx.x;
    const int b0  = blockIdx.x * 2;        // batch pair
    const int fh  = blockIdx.y;            // filter half (0/1)

    // ---- Phase 1: zero slab, then fill interior from X (coalesced) ----
    float4* s4 = (float4*)slab;
#pragma unroll 1
    for (int i = tid; i < (PPIX * 2) / 4; i += 128)
        s4[i] = make_float4(0.f, 0.f, 0.f, 0.f);
    __syncthreads();

#pragma unroll
    for (int q = 0; q < 2; q++) {
        const float4* src = (const float4*)(X + (size_t)(b0 + q) * PIX);
#pragma unroll 1
        for (int i = tid; i < PIX / 4; i += 128) {
            const float4 v = src[i];
            const int p = i * 4;
            const int y = p >> 6, x = p & 63;   // rows are 64 wide, 4 | 64
            const int s = ((y + PAD) * PW + (x + PAD)) * 2 + q;
            slab[s]     = v.x;
            slab[s + 2] = v.y;
            slab[s + 4] = v.z;
            slab[s + 6] = v.w;
        }
    }
    __syncthreads();

    // ---- Phase 2: filter sweep (slab is read-only; no more barriers) ----
    const unsigned long long* slab2 = (const unsigned long long*)slab;

#pragma unroll 1
    for (int it = 0; it < FITER; it++) {
        const int f  = fh * FHALF + it * 128 + tid;
        const int pi = __ldg(&pos[2 * f]);
        const int pj = __ldg(&pos[2 * f + 1]);
        const unsigned long long* win = slab2 + (pi * PW + pj);

        // Broadcast-pack 25 weights (L1-resident across blocks).
        unsigned long long wp[25];
#pragma unroll
        for (int k = 0; k < 25; k++) {
            const float w = __ldg(&W[f * 25 + k]);
            wp[k] = pack2(w, w);
        }

        // 6x6 packed accumulators; first touch (ky==0, kx==0) is a MUL so
        // no explicit zero-init is needed.
        unsigned long long acc[36];

#pragma unroll
        for (int r = 0; r < 10; r++) {
            unsigned long long row[10];
#pragma unroll
            for (int c = 0; c < 10; c++)
                row[c] = win[r * PW + c];     // LDS.64, immediate offset

#pragma unroll
            for (int oy = 0; oy < 6; oy++) {
                const int ky = r - oy;
                if (ky < 0 || ky > 4) continue;   // compile-time pruned
#pragma unroll
                for (int ox = 0; ox < 6; ox++) {
#pragma unroll
                    for (int kx = 0; kx < 5; kx++) {
                        if (ky == 0 && kx == 0)
                            acc[oy * 6 + ox] = fmul2(row[ox], wp[0]);
                        else
                            acc[oy * 6 + ox] = ffma2(row[ox + kx],
                                                     wp[ky * 5 + kx],
                                                     acc[oy * 6 + ox]);
                    }
                }
            }
        }

        // ---- bias + 3x3 stride-3 maxpool -> 2x2, one float4 per batch ----
        const float bv = __ldg(&bias[f]);
        float m0[4], m1[4];
#pragma unroll
        for (int py = 0; py < 2; py++) {
#pragma unroll
            for (int px = 0; px < 2; px++) {
                float a0 = -FLT_MAX, a1 = -FLT_MAX;
#pragma unroll
                for (int dy = 0; dy < 3; dy++) {
#pragma unroll
                    for (int dx = 0; dx < 3; dx++) {
                        const float2 v =
                            unpack2(acc[(3 * py + dy) * 6 + (3 * px + dx)]);
                        a0 = fmaxf(a0, v.x);
                        a1 = fmaxf(a1, v.y);
                    }
                }
                m0[py * 2 + px] = a0 + bv;
                m1[py * 2 + px] = a1 + bv;
            }
        }

        // out[b, f*4 + j]; lanes = consecutive f -> contiguous 512B stores.
        float4* o0 = (float4*)(out + (size_t)b0 * (NF * 4) + f * 4);
        float4* o1 = (float4*)(out + (size_t)(b0 + 1) * (NF * 4) + f * 4);
        *o0 = make_float4(m0[0], m0[1], m0[2], m0[3]);
        *o1 = make_float4(m1[0], m1[1], m1[2], m1[3]);
    }
}

// ---------------------------------------------------------------------------
// kernel_launch: ONE fused kernel. Graph-capturable, allocation-free.
// ---------------------------------------------------------------------------
extern "C" void kernel_launch(void* const* d_in, const int* in_sizes, int n_in,
                              void* d_out, int out_size) {
    (void)in_sizes; (void)n_in; (void)out_size;
    const float* X    = (const float*)d_in[0];
    const float* W    = (const float*)d_in[1];
    const float* bias = (const float*)d_in[2];
    const int*   pos  = (const int*)d_in[3];
    float*       out  = (float*)d_out;

    dim3 grid(BATCH / 2, 2);     // (512 pairs, 2 filter-halves) = 1024 blocks
    filters_fused_kernel<<<grid, 128>>>(X, W, bias, pos, out);
}

// round 6
// speedup vs baseline: 1.0006x; 1.0006x over previous
#include <cuda_runtime.h>
#include <cstdint>
#include <cfloat>

// Problem constants
#define NF    1024
#define BATCH 1024
#define HW    64
#define PIX   (HW * HW)     // 4096
#define PAD   3
#define PW    70            // padded side
#define PPIX  (PW * PW)     // 4900
#define FHALF 512           // filters per block
#define FITER 4             // 512 / 128 threads

// ---------------------------------------------------------------------------
// Packed f32x2 helpers (Blackwell packed-FP32 pipe: 2x FFMA throughput)
// ---------------------------------------------------------------------------
__device__ __forceinline__ unsigned long long ffma2(unsigned long long a,
                                                    unsigned long long b,
                                                    unsigned long long c) {
    unsigned long long d;
    asm("fma.rn.f32x2 %0, %1, %2, %3;" : "=l"(d) : "l"(a), "l"(b), "l"(c));
    return d;
}
__device__ __forceinline__ unsigned long long fmul2(unsigned long long a,
                                                    unsigned long long b) {
    unsigned long long d;
    asm("mul.rn.f32x2 %0, %1, %2;" : "=l"(d) : "l"(a), "l"(b));
    return d;
}
__device__ __forceinline__ unsigned long long pack2(float x, float y) {
    unsigned long long r;
    asm("mov.b64 %0, {%1, %2};" : "=l"(r) : "f"(x), "f"(y));
    return r;
}
__device__ __forceinline__ float2 unpack2(unsigned long long v) {
    float2 r;
    asm("mov.b64 {%0, %1}, %2;" : "=f"(r.x), "=f"(r.y) : "l"(v));
    return r;
}

// ---------------------------------------------------------------------------
// Fused kernel: block = (batch-pair, filter-half).
//  1. Build zero-padded 70x70x2 image slab in SMEM from X (coalesced).
//  2. For each of 512 filters: 5x5 conv on the 6x6 outputs the pool reads
//     (window rows via LDS.64 immediate-offset), bias + 3x3/3 maxpool, store.
// All math is packed f32x2 (lane .x = batch b0, .y = b0+1).
// ---------------------------------------------------------------------------
__global__ void __launch_bounds__(128, 3) filters_fused_kernel(
    const float* __restrict__ X,      // [B, 4096]
    const float* __restrict__ W,      // [NF, 25]
    const float* __restrict__ bias,   // [NF]
    const int*   __restrict__ pos,    // [NF, 2]
    float*       __restrict__ out)    // [B, NF*4]
{
    __shared__ float slab[PPIX * 2];  // [padded_pixel][2 batches] = 39.2 KB

    const int tid = threadIdx.x;
    const int b0  = blockIdx.x * 2;        // batch pair
    const int fh  = blockIdx.y;            // filter half (0/1)

    // ---- Phase 1: zero slab, then fill interior from X (coalesced) ----
    float4* s4 = (float4*)slab;
#pragma unroll 1
    for (int i = tid; i < (PPIX * 2) / 4; i += 128)
        s4[i] = make_float4(0.f, 0.f, 0.f, 0.f);
    __syncthreads();

#pragma unroll
    for (int q = 0; q < 2; q++) {
        const float4* src = (const float4*)(X + (size_t)(b0 + q) * PIX);
#pragma unroll 1
        for (int i = tid; i < PIX / 4; i += 128) {
            const float4 v = src[i];
            const int p = i * 4;
            const int y = p >> 6, x = p & 63;   // rows are 64 wide, 4 | 64
            const int s = ((y + PAD) * PW + (x + PAD)) * 2 + q;
            slab[s]     = v.x;
            slab[s + 2] = v.y;
            slab[s + 4] = v.z;
            slab[s + 6] = v.w;
        }
    }
    __syncthreads();

    // ---- Phase 2: filter sweep (slab is read-only; no more barriers) ----
    const unsigned long long* slab2 = (const unsigned long long*)slab;

#pragma unroll 1
    for (int it = 0; it < FITER; it++) {
        const int f  = fh * FHALF + it * 128 + tid;
        const int pi = __ldg(&pos[2 * f]);
        const int pj = __ldg(&pos[2 * f + 1]);
        const unsigned long long* win = slab2 + (pi * PW + pj);

        // Broadcast-pack 25 weights (L1-resident across blocks).
        unsigned long long wp[25];
#pragma unroll
        for (int k = 0; k < 25; k++) {
            const float w = __ldg(&W[f * 25 + k]);
            wp[k] = pack2(w, w);
        }

        // 6x6 packed accumulators; first touch (ky==0, kx==0) is a MUL so
        // no explicit zero-init is needed.
        unsigned long long acc[36];

#pragma unroll
        for (int r = 0; r < 10; r++) {
            unsigned long long row[10];
#pragma unroll
            for (int c = 0; c < 10; c++)
                row[c] = win[r * PW + c];     // LDS.64, immediate offset

#pragma unroll
            for (int oy = 0; oy < 6; oy++) {
                const int ky = r - oy;
                if (ky < 0 || ky > 4) continue;   // compile-time pruned
#pragma unroll
                for (int ox = 0; ox < 6; ox++) {
#pragma unroll
                    for (int kx = 0; kx < 5; kx++) {
                        if (ky == 0 && kx == 0)
                            acc[oy * 6 + ox] = fmul2(row[ox], wp[0]);
                        else
                            acc[oy * 6 + ox] = ffma2(row[ox + kx],
                                                     wp[ky * 5 + kx],
                                                     acc[oy * 6 + ox]);
                    }
                }
            }
        }

        // ---- bias + 3x3 stride-3 maxpool -> 2x2, one float4 per batch ----
        const float bv = __ldg(&bias[f]);
        float m0[4], m1[4];
#pragma unroll
        for (int py = 0; py < 2; py++) {
#pragma unroll
            for (int px = 0; px < 2; px++) {
                float a0 = -FLT_MAX, a1 = -FLT_MAX;
#pragma unroll
                for (int dy = 0; dy < 3; dy++) {
#pragma unroll
                    for (int dx = 0; dx < 3; dx++) {
                        const float2 v =
                            unpack2(acc[(3 * py + dy) * 6 + (3 * px + dx)]);
                        a0 = fmaxf(a0, v.x);
                        a1 = fmaxf(a1, v.y);
                    }
                }
                m0[py * 2 + px] = a0 + bv;
                m1[py * 2 + px] = a1 + bv;
            }
        }

        // out[b, f*4 + j]; lanes = consecutive f -> contiguous 512B stores.
        float4* o0 = (float4*)(out + (size_t)b0 * (NF * 4) + f * 4);
        float4* o1 = (float4*)(out + (size_t)(b0 + 1) * (NF * 4) + f * 4);
        *o0 = make_float4(m0[0], m0[1], m0[2], m0[3]);
        *o1 = make_float4(m1[0], m1[1], m1[2], m1[3]);
    }
}

// ---------------------------------------------------------------------------
// kernel_launch: ONE fused kernel. Graph-capturable, allocation-free.
// ---------------------------------------------------------------------------
extern "C" void kernel_launch(void* const* d_in, const int* in_sizes, int n_in,
                              void* d_out, int out_size) {
    (void)in_sizes; (void)n_in; (void)out_size;
    const float* X    = (const float*)d_in[0];
    const float* W    = (const float*)d_in[1];
    const float* bias = (const float*)d_in[2];
    const int*   pos  = (const int*)d_in[3];
    float*       out  = (float*)d_out;

    dim3 grid(BATCH / 2, 2);     // (512 pairs, 2 filter-halves) = 1024 blocks
    filters_fused_kernel<<<grid, 128>>>(X, W, bias, pos, out);
}